// round 8
// baseline (speedup 1.0000x reference)
#include <cuda_runtime.h>
#include <cuda_bf16.h>
#include <cstdint>

typedef unsigned long long ull;

#define NBLK 128
#define NTHR 256
#define AS_PAD 36

// ---- persistent device state (no allocation) ----
__device__ float g_hA[2][16384];
__device__ float g_cA[16384];
__device__ float g_h1[2][16384];
__device__ float g_c1[16384];
__device__ float g_h2[2][16384];
__device__ float g_c2[16384];
__device__ float g_ctx[16384];
__device__ float g_sc[16384];
__device__ float g_pmax[128];
__device__ float g_psum[128];
__device__ unsigned g_cnt;
__device__ volatile unsigned g_gen;

// smem layout (bytes)
#define OFF_AS   0
#define OFF_WS   147456
#define OFF_RED  212992
#define OFF_ZB   215040
#define SMEM_BYTES 217088

__device__ __forceinline__ ull f2pack(float lo, float hi) {
    ull r;
    asm("mov.b64 %0, {%1, %2};" : "=l"(r) : "r"(__float_as_uint(lo)), "r"(__float_as_uint(hi)));
    return r;
}
__device__ __forceinline__ void ffma2(ull& d, ull a, ull b) {
    asm("fma.rn.f32x2 %0, %1, %2, %0;" : "+l"(d) : "l"(a), "l"(b));
}
__device__ __forceinline__ void fadd2(ull& d, ull a) {
    asm("add.rn.f32x2 %0, %1, %0;" : "+l"(d) : "l"(a));
}

__device__ __forceinline__ void gbar() {
    __syncthreads();
    if (threadIdx.x == 0) {
        unsigned gen = g_gen;
        __threadfence();
        if (atomicAdd(&g_cnt, 1u) == (unsigned)(NBLK - 1)) {
            g_cnt = 0;
            __threadfence();
            g_gen = gen + 1u;
        } else {
            while (g_gen == gen) __nanosleep(64);
        }
        __threadfence();
    }
    __syncthreads();
}

// One LSTM cell stage. z = [in ; hrec] @ [W ; R] + bias, gates i,f,g,o; this CTA
// owns u in [u0, u0+4): 16 gate columns -> CTA-local cell update.
__device__ void cell(const float* __restrict__ in0, long long instride,
                     const float* __restrict__ hrec,
                     float* __restrict__ c_st, float* __restrict__ h_out,
                     const float* __restrict__ W, const float* __restrict__ R,
                     const float* __restrict__ bias, int u0, char* smraw) {
    float* As  = (float*)(smraw + OFF_AS);    // [1024][36]
    float* Wsm = (float*)(smraw + OFF_WS);    // [1024][16]
    ull*   red = (ull*)  (smraw + OFF_RED);   // [128][2]
    float* zb  = (float*)(smraw + OFF_ZB);    // [16][32]
    const int tid  = threadIdx.x;
    const int lane = tid & 31, warp = tid >> 5;

    // Stage A: rows 0..511 input vec, 512..1023 recurrent h. Warp-per-batch-row,
    // coalesced global loads, 4-way-conflict smem stores (cheap vs GEMM).
    #pragma unroll
    for (int mi = 0; mi < 4; ++mi) {
        int m = warp + mi * 8;
        const float* s0 = in0 + (long long)m * instride;
        const float* s1 = hrec + m * 512;
        #pragma unroll 4
        for (int kk = lane; kk < 512; kk += 32) {
            As[kk * AS_PAD + m]           = __ldcg(s0 + kk);
            As[(kk + 512) * AS_PAD + m]   = __ldcg(s1 + kk);
        }
    }
    // Stage W slice: columns {u0+q + 512*g}, jj = 4g+q, float4 per (k,g).
    #pragma unroll 4
    for (int i = tid; i < 4096; i += NTHR) {
        int k = i >> 2, g = i & 3;
        const float* src = (k < 512 ? W + (size_t)k * 2048
                                    : R + (size_t)(k - 512) * 2048) + u0 + (g << 9);
        float4 v = __ldg((const float4*)src);
        *(float4*)(Wsm + k * 16 + (g << 2)) = v;
    }
    __syncthreads();

    // GEMM: thread = (ksplit-half, mg in 0..7, jj in 0..15); 4m x 1j tile, f32x2.
    const int half = tid >> 7, r = tid & 127;
    const int jj = r & 15, mg = r >> 4, m0 = mg << 2;
    const float* Ab = As + half * 512 * AS_PAD + m0;
    const float* Wb = Wsm + half * 512 * 16 + jj;
    ull a0 = 0ull, a1 = 0ull;
    #pragma unroll 8
    for (int k = 0; k < 512; ++k) {
        float w = Wb[k * 16];
        ull wv = f2pack(w, w);
        ulonglong2 av = *(const ulonglong2*)(Ab + k * AS_PAD);
        ffma2(a0, av.x, wv);
        ffma2(a1, av.y, wv);
    }
    if (half) { red[r * 2] = a0; red[r * 2 + 1] = a1; }
    __syncthreads();
    if (!half) {
        fadd2(a0, red[r * 2]);
        fadd2(a1, red[r * 2 + 1]);
        *(ull*)(zb + jj * 32 + m0)     = a0;
        *(ull*)(zb + jj * 32 + m0 + 2) = a1;
    }
    __syncthreads();

    if (tid < 128) {
        int m = tid & 31, q = tid >> 5;
        int u = u0 + q;
        float zi = zb[(q     ) * 32 + m] + __ldg(bias + u);
        float zf = zb[(4  + q) * 32 + m] + __ldg(bias + u + 512);
        float zg = zb[(8  + q) * 32 + m] + __ldg(bias + u + 1024);
        float zo = zb[(12 + q) * 32 + m] + __ldg(bias + u + 1536);
        float ig = 1.f / (1.f + expf(-zi));
        float fg = 1.f / (1.f + expf(-zf));
        float gg = tanhf(zg);
        float og = 1.f / (1.f + expf(-zo));
        float cv = fg * __ldcg(c_st + m * 512 + u) + ig * gg;
        c_st[m * 512 + u]  = cv;
        h_out[m * 512 + u] = og * tanhf(cv);
    }
    __syncthreads();
}

__global__ void __launch_bounds__(NTHR, 1)
spk(const float* __restrict__ x,  const float* __restrict__ y,
    const float* __restrict__ Wa, const float* __restrict__ Ra, const float* __restrict__ ba,
    const float* __restrict__ W1, const float* __restrict__ R1, const float* __restrict__ b1,
    const float* __restrict__ W2, const float* __restrict__ R2, const float* __restrict__ b2,
    const float* __restrict__ Wd, const float* __restrict__ bd,
    float* __restrict__ out) {
    extern __shared__ char smraw[];
    const int blk = blockIdx.x, tid = threadIdx.x;
    const int lane = tid & 31, warp = tid >> 5;
    const int u0 = blk * 4;

    // ---- zero initial states (device globals persist across graph replays) ----
    {
        float* bufs[9] = {g_hA[0], g_hA[1], g_cA, g_h1[0], g_h1[1], g_c1,
                          g_h2[0], g_h2[1], g_c2};
        int base = blk * NTHR + tid;
        #pragma unroll
        for (int a = 0; a < 9; ++a)
            for (int i = base; i < 16384; i += NBLK * NTHR) bufs[a][i] = 0.f;
    }
    gbar();

    for (int t = 0; t < 130; ++t) {
        // ---------- stage 1: pipelined cells ----------
        if (t < 128)
            cell(y + (size_t)t * 512, 128LL * 512, g_hA[(t + 1) & 1],
                 g_cA, g_hA[t & 1], Wa, Ra, ba, u0, smraw);
        if (t >= 1 && t <= 128)
            cell(g_ctx, 512LL, g_h1[(t + 1) & 1],
                 g_c1, g_h1[t & 1], W1, R1, b1, u0, smraw);
        if (t >= 2)
            cell(g_h1[(t + 1) & 1], 512LL, g_h2[(t + 1) & 1],
                 g_c2, g_h2[t & 1], W2, R2, b2, u0, smraw);
        gbar();

        // ---------- phase S: scores + partial softmax stats ----------
        if (t < 128) {
            int b = blk >> 2, sq = blk & 3;
            float* hs   = (float*)smraw;        // 512
            float* sc   = hs + 512;             // 128
            float* wred = sc + 128;             // 8
            const float* hA = g_hA[t & 1] + b * 512;
            for (int i = tid; i < 512; i += NTHR) hs[i] = __ldcg(hA + i);
            __syncthreads();
            #pragma unroll 4
            for (int si = 0; si < 16; ++si) {
                int sl = warp + si * 8;
                const float4* xr = (const float4*)(x + ((size_t)(b * 512 + sq * 128 + sl)) * 512);
                const float4* hr = (const float4*)hs;
                float acc = 0.f;
                #pragma unroll
                for (int i2 = 0; i2 < 4; ++i2) {
                    float4 xv = __ldg(xr + lane + 32 * i2);
                    float4 hv = hr[lane + 32 * i2];
                    acc += xv.x * hv.x + xv.y * hv.y + xv.z * hv.z + xv.w * hv.w;
                }
                #pragma unroll
                for (int o = 16; o; o >>= 1) acc += __shfl_xor_sync(0xffffffffu, acc, o);
                if (lane == 0) sc[sl] = acc;
            }
            __syncthreads();
            float v = (tid < 128) ? sc[tid] : -1e30f;
            #pragma unroll
            for (int o = 16; o; o >>= 1) v = fmaxf(v, __shfl_xor_sync(0xffffffffu, v, o));
            if (lane == 0) wred[warp] = v;
            __syncthreads();
            float M = wred[0];
            #pragma unroll
            for (int w2 = 1; w2 < 8; ++w2) M = fmaxf(M, wred[w2]);
            __syncthreads();
            float e = (tid < 128) ? expf(sc[tid] - M) : 0.f;
            #pragma unroll
            for (int o = 16; o; o >>= 1) e += __shfl_xor_sync(0xffffffffu, e, o);
            if (lane == 0) wred[warp] = e;
            __syncthreads();
            if (tid < 128) g_sc[b * 512 + sq * 128 + tid] = sc[tid];
            if (tid == 0) {
                float S = 0.f;
                #pragma unroll
                for (int w2 = 0; w2 < 8; ++w2) S += wred[w2];
                g_pmax[b * 4 + sq] = M;
                g_psum[b * 4 + sq] = S;
            }
        }
        gbar();

        // ---------- phase X: global softmax, ctx slice, residual ----------
        if (t < 128) {
            int b = blk >> 2, uq = blk & 3, u0x = uq * 128;
            float M = -1e30f;
            float pm[4], ps[4];
            #pragma unroll
            for (int q = 0; q < 4; ++q) {
                pm[q] = __ldcg(g_pmax + b * 4 + q);
                ps[q] = __ldcg(g_psum + b * 4 + q);
                M = fmaxf(M, pm[q]);
            }
            float S = 0.f;
            #pragma unroll
            for (int q = 0; q < 4; ++q) S += ps[q] * expf(pm[q] - M);
            float invS = 1.f / S;
            float* ws   = (float*)smraw;   // 512 weights
            float* redx = ws + 512;        // 128
            for (int s = tid; s < 512; s += NTHR)
                ws[s] = expf(__ldcg(g_sc + b * 512 + s) - M) * invS;
            __syncthreads();
            int ui = tid & 127, sh = tid >> 7;
            int u = u0x + ui;
            const float* xc = x + ((size_t)b * 512 + sh * 256) * 512 + u;
            float acc = 0.f;
            #pragma unroll 4
            for (int s = 0; s < 256; ++s)
                acc += ws[sh * 256 + s] * __ldg(xc + (size_t)s * 512);
            if (sh) redx[ui] = acc;
            __syncthreads();
            if (!sh) {
                float ctxv = acc + redx[ui];
                int idx = b * 512 + u;
                g_ctx[idx] = ctxv;
                g_hA[t & 1][idx] = __ldcg(&g_hA[t & 1][idx]) + ctxv;
                g_cA[idx]        = __ldcg(&g_cA[idx]) + ctxv;
            }
            __syncthreads();
        }
        gbar();
    }

    // ---------- final dense 512->46 + softmax (hT = g_h2[129&1] = g_h2[1]) ----------
    if (blk < 32) {
        int b = blk;
        float* hs = (float*)smraw;
        float* lg = hs + 512;
        for (int i = tid; i < 512; i += NTHR) hs[i] = __ldcg(g_h2[1] + b * 512 + i);
        __syncthreads();
        for (int v = warp; v < 46; v += 8) {
            float acc = 0.f;
            #pragma unroll 4
            for (int k = lane; k < 512; k += 32)
                acc += hs[k] * __ldg(Wd + (size_t)k * 46 + v);
            #pragma unroll
            for (int o = 16; o; o >>= 1) acc += __shfl_xor_sync(0xffffffffu, acc, o);
            if (lane == 0) lg[v] = acc + __ldg(bd + v);
        }
        __syncthreads();
        if (tid == 0) {
            float M = lg[0];
            for (int v = 1; v < 46; ++v) M = fmaxf(M, lg[v]);
            float S = 0.f;
            for (int v = 0; v < 46; ++v) { float e = expf(lg[v] - M); lg[v] = e; S += e; }
            float inv = 1.f / S;
            for (int v = 0; v < 46; ++v) out[b * 46 + v] = lg[v] * inv;
        }
    }
}

extern "C" void kernel_launch(void* const* d_in, const int* in_sizes, int n_in,
                              void* d_out, int out_size) {
    const float* x  = (const float*)d_in[0];
    const float* y  = (const float*)d_in[1];
    const float* Wa = (const float*)d_in[2];
    const float* Ra = (const float*)d_in[3];
    const float* ba = (const float*)d_in[4];
    const float* W1 = (const float*)d_in[5];
    const float* R1 = (const float*)d_in[6];
    const float* b1 = (const float*)d_in[7];
    const float* W2 = (const float*)d_in[8];
    const float* R2 = (const float*)d_in[9];
    const float* b2 = (const float*)d_in[10];
    const float* Wd = (const float*)d_in[11];
    const float* bd = (const float*)d_in[12];
    cudaFuncSetAttribute(spk, cudaFuncAttributeMaxDynamicSharedMemorySize, SMEM_BYTES);
    spk<<<NBLK, NTHR, SMEM_BYTES>>>(x, y, Wa, Ra, ba, W1, R1, b1, W2, R2, b2,
                                    Wd, bd, (float*)d_out);
}

// round 9
// speedup vs baseline: 1.5811x; 1.5811x over previous
#include <cuda_runtime.h>
#include <cuda_bf16.h>
#include <cstdint>

typedef unsigned long long ull;

#define NBLK 128
#define NTHR 256

// ---- persistent device state (no allocation) ----
__device__ float g_hA[2][16384];
__device__ float g_cA[16384];
__device__ float g_h1[2][16384];
__device__ float g_c1[16384];
__device__ float g_h2[2][16384];
__device__ float g_c2[16384];
__device__ float g_ctx[16384];
__device__ float g_sc[16384];
__device__ float g_pmax[128];
__device__ float g_psum[128];
__device__ unsigned g_cnt;
__device__ volatile unsigned g_gen;

// ---- dynamic smem layout (float offsets) ----
#define WJ      1028              // padded k-stride per column (2-way max conflict)
#define WCELL   (16 * WJ)         // 16448 floats per cell
#define W_OFF   0                 // 3 cells: 49344 floats (197,376 B), persistent
#define A_OFF   (3 * WCELL)       // A chunk [32][132] = 4224 floats
#define AROW    132
#define ZB_OFF  (A_OFF + 32 * AROW)   // z buffer [16][32] = 512 floats
#define SCR_OFF A_OFF             // attention/final scratch overlays A chunk
#define SMEM_FLOATS (ZB_OFF + 512)
#define SMEM_BYTES  (SMEM_FLOATS * 4)  // 216,320 B

__device__ __forceinline__ void ffma2(ull& d, ull a, ull b) {
    asm("fma.rn.f32x2 %0, %1, %2, %0;" : "+l"(d) : "l"(a), "l"(b));
}
__device__ __forceinline__ void fadd2(ull& d, ull a) {
    asm("add.rn.f32x2 %0, %1, %0;" : "+l"(d) : "l"(a));
}
__device__ __forceinline__ float2 ull2f2(ull v) {
    float2 r;
    asm("mov.b64 {%0, %1}, %2;" : "=f"(r.x), "=f"(r.y) : "l"(v));
    return r;
}

__device__ __forceinline__ void gbar() {
    __syncthreads();
    if (threadIdx.x == 0) {
        unsigned gen = g_gen;
        __threadfence();
        if (atomicAdd(&g_cnt, 1u) == (unsigned)(NBLK - 1)) {
            g_cnt = 0;
            __threadfence();
            g_gen = gen + 1u;
        } else {
            while (g_gen == gen) __nanosleep(64);
        }
        __threadfence();
    }
    __syncthreads();
}

// One LSTM cell. z = [in ; hrec] @ [W ; R] + bias (K=1024, this CTA's 16 gate
// cols), gates i,f,g,o; CTA owns u in [u0, u0+4). Weights already resident in
// smem at W_OFF + cellIdx*WCELL, layout [jj][k] (k-contiguous, pad 1028).
__device__ void cell(const float* __restrict__ in0, long long instride,
                     const float* __restrict__ hrec,
                     float* __restrict__ c_st, float* __restrict__ h_out,
                     const float* __restrict__ bias,
                     int cellIdx, int u0, float* __restrict__ sm) {
    float* Wsm = sm + W_OFF + cellIdx * WCELL;
    float* A_s = sm + A_OFF;
    float* zb  = sm + ZB_OFF;
    const int tid = threadIdx.x;
    const int am = tid >> 3, akq = tid & 7;         // A staging: row, k-quad
    const int jj = tid & 15, mp = tid >> 4, m0 = mp * 2;

    float4 pf[4];
    // fetch chunk 0 (k 0..127, always from in0)
    {
        const float* src = in0 + (long long)am * instride + akq * 4;
        #pragma unroll
        for (int j = 0; j < 4; ++j) pf[j] = __ldcg((const float4*)(src + j * 32));
    }
    #pragma unroll
    for (int j = 0; j < 4; ++j)
        *(float4*)(A_s + am * AROW + akq * 4 + j * 32) = pf[j];
    __syncthreads();

    ull acc0a = 0ull, acc0b = 0ull, acc1a = 0ull, acc1b = 0ull;
    #pragma unroll 1
    for (int c = 0; c < 8; ++c) {
        if (c < 7) {
            const int cn = c + 1;
            const float* base = (cn < 4)
                ? (in0 + (long long)am * instride + cn * 128)
                : (hrec + am * 512 + (cn - 4) * 128);
            const float* src = base + akq * 4;
            #pragma unroll
            for (int j = 0; j < 4; ++j) pf[j] = __ldcg((const float4*)(src + j * 32));
        }
        const ulonglong2* Wp  = (const ulonglong2*)(Wsm + jj * WJ + c * 128);
        const ulonglong2* Ap0 = (const ulonglong2*)(A_s + m0 * AROW);
        const ulonglong2* Ap1 = (const ulonglong2*)(A_s + (m0 + 1) * AROW);
        #pragma unroll 8
        for (int kk = 0; kk < 32; ++kk) {
            ulonglong2 wv = Wp[kk];
            ulonglong2 a0 = Ap0[kk];
            ulonglong2 a1 = Ap1[kk];
            ffma2(acc0a, a0.x, wv.x); ffma2(acc0b, a0.y, wv.y);
            ffma2(acc1a, a1.x, wv.x); ffma2(acc1b, a1.y, wv.y);
        }
        __syncthreads();
        if (c < 7) {
            #pragma unroll
            for (int j = 0; j < 4; ++j)
                *(float4*)(A_s + am * AROW + akq * 4 + j * 32) = pf[j];
            __syncthreads();
        }
    }
    fadd2(acc0a, acc0b);
    fadd2(acc1a, acc1b);
    float2 p0 = ull2f2(acc0a), p1 = ull2f2(acc1a);
    *(float2*)(zb + jj * 32 + m0) = make_float2(p0.x + p0.y, p1.x + p1.y);
    __syncthreads();

    if (tid < 128) {
        int m = tid & 31, q = tid >> 5;
        int u = u0 + q;
        float zi = zb[(q     ) * 32 + m] + __ldg(bias + u);
        float zf = zb[(4  + q) * 32 + m] + __ldg(bias + u + 512);
        float zg = zb[(8  + q) * 32 + m] + __ldg(bias + u + 1024);
        float zo = zb[(12 + q) * 32 + m] + __ldg(bias + u + 1536);
        float ig = 1.f / (1.f + expf(-zi));
        float fg = 1.f / (1.f + expf(-zf));
        float gg = tanhf(zg);
        float og = 1.f / (1.f + expf(-zo));
        float cv = fg * __ldcg(c_st + m * 512 + u) + ig * gg;
        c_st[m * 512 + u]  = cv;
        h_out[m * 512 + u] = og * tanhf(cv);
    }
    __syncthreads();
}

__global__ void __launch_bounds__(NTHR, 1)
spk(const float* __restrict__ x,  const float* __restrict__ y,
    const float* __restrict__ Wa, const float* __restrict__ Ra, const float* __restrict__ ba,
    const float* __restrict__ W1, const float* __restrict__ R1, const float* __restrict__ b1,
    const float* __restrict__ W2, const float* __restrict__ R2, const float* __restrict__ b2,
    const float* __restrict__ Wd, const float* __restrict__ bd,
    float* __restrict__ out) {
    extern __shared__ float sm[];
    const int blk = blockIdx.x, tid = threadIdx.x;
    const int lane = tid & 31, warp = tid >> 5;
    const int u0 = blk * 4;

    // ---- one-time persistent weight load: Wsm[c][jj][k] = stacked [W;R] col slice ----
    {
        const float* Ws[3] = {Wa, W1, W2};
        const float* Rs[3] = {Ra, R1, R2};
        #pragma unroll
        for (int c = 0; c < 3; ++c) {
            const float* Wc = Ws[c];
            const float* Rc = Rs[c];
            for (int i = tid; i < 16384; i += NTHR) {
                int k = i >> 4, j = i & 15;
                int col = u0 + (j & 3) + ((j >> 2) << 9);
                float v = (k < 512) ? __ldg(Wc + (size_t)k * 2048 + col)
                                    : __ldg(Rc + (size_t)(k - 512) * 2048 + col);
                sm[c * WCELL + j * WJ + k] = v;
            }
        }
    }

    // ---- zero initial states (globals persist across graph replays) ----
    {
        float* bufs[9] = {g_hA[0], g_hA[1], g_cA, g_h1[0], g_h1[1], g_c1,
                          g_h2[0], g_h2[1], g_c2};
        int base = blk * NTHR + tid;
        #pragma unroll
        for (int a = 0; a < 9; ++a)
            for (int i = base; i < 16384; i += NBLK * NTHR) bufs[a][i] = 0.f;
    }
    gbar();

    for (int t = 0; t < 130; ++t) {
        // ---------- stage 1: software-pipelined cells ----------
        if (t < 128)
            cell(y + (size_t)t * 512, 128LL * 512, g_hA[(t + 1) & 1],
                 g_cA, g_hA[t & 1], ba, 0, u0, sm);
        if (t >= 1 && t <= 128)
            cell(g_ctx, 512LL, g_h1[(t + 1) & 1],
                 g_c1, g_h1[t & 1], b1, 1, u0, sm);
        if (t >= 2)
            cell(g_h1[(t + 1) & 1], 512LL, g_h2[(t + 1) & 1],
                 g_c2, g_h2[t & 1], b2, 2, u0, sm);
        gbar();

        // ---------- phase S: scores + partial softmax stats ----------
        if (t < 128) {
            int b = blk >> 2, sq = blk & 3;
            float* hs   = sm + SCR_OFF;     // 512
            float* sc   = hs + 512;         // 128
            float* wred = sc + 128;         // 8
            const float* hA = g_hA[t & 1] + b * 512;
            for (int i = tid; i < 512; i += NTHR) hs[i] = __ldcg(hA + i);
            __syncthreads();
            const float4* hr = (const float4*)hs;
            float4 hv[4];
            #pragma unroll
            for (int i2 = 0; i2 < 4; ++i2) hv[i2] = hr[lane + 32 * i2];
            #pragma unroll 1
            for (int si = 0; si < 16; si += 2) {
                int sl0 = warp + si * 8;
                const float4* xr0 = (const float4*)(x + ((size_t)(b * 512 + sq * 128 + sl0)) * 512);
                const float4* xr1 = xr0 + 8 * 128;
                float4 x0[4], x1[4];
                #pragma unroll
                for (int i2 = 0; i2 < 4; ++i2) {
                    x0[i2] = __ldg(xr0 + lane + 32 * i2);
                    x1[i2] = __ldg(xr1 + lane + 32 * i2);
                }
                float a0 = 0.f, a1 = 0.f;
                #pragma unroll
                for (int i2 = 0; i2 < 4; ++i2) {
                    a0 += x0[i2].x * hv[i2].x + x0[i2].y * hv[i2].y
                        + x0[i2].z * hv[i2].z + x0[i2].w * hv[i2].w;
                    a1 += x1[i2].x * hv[i2].x + x1[i2].y * hv[i2].y
                        + x1[i2].z * hv[i2].z + x1[i2].w * hv[i2].w;
                }
                #pragma unroll
                for (int o = 16; o; o >>= 1) {
                    a0 += __shfl_xor_sync(0xffffffffu, a0, o);
                    a1 += __shfl_xor_sync(0xffffffffu, a1, o);
                }
                if (lane == 0) { sc[sl0] = a0; sc[sl0 + 8] = a1; }
            }
            __syncthreads();
            float v = (tid < 128) ? sc[tid] : -1e30f;
            #pragma unroll
            for (int o = 16; o; o >>= 1) v = fmaxf(v, __shfl_xor_sync(0xffffffffu, v, o));
            if (lane == 0) wred[warp] = v;
            __syncthreads();
            float M = wred[0];
            #pragma unroll
            for (int w2 = 1; w2 < 8; ++w2) M = fmaxf(M, wred[w2]);
            __syncthreads();
            float e = (tid < 128) ? expf(sc[tid] - M) : 0.f;
            #pragma unroll
            for (int o = 16; o; o >>= 1) e += __shfl_xor_sync(0xffffffffu, e, o);
            if (lane == 0) wred[warp] = e;
            __syncthreads();
            if (tid < 128) g_sc[b * 512 + sq * 128 + tid] = sc[tid];
            if (tid == 0) {
                float S = 0.f;
                #pragma unroll
                for (int w2 = 0; w2 < 8; ++w2) S += wred[w2];
                g_pmax[b * 4 + sq] = M;
                g_psum[b * 4 + sq] = S;
            }
        }
        gbar();

        // ---------- phase X: global softmax, ctx slice, residual ----------
        if (t < 128) {
            int b = blk >> 2, uq = blk & 3;
            float pm[4], ps[4], M = -1e30f;
            #pragma unroll
            for (int q = 0; q < 4; ++q) {
                pm[q] = __ldcg(g_pmax + b * 4 + q);
                ps[q] = __ldcg(g_psum + b * 4 + q);
                M = fmaxf(M, pm[q]);
            }
            float S = 0.f;
            #pragma unroll
            for (int q = 0; q < 4; ++q) S += ps[q] * expf(pm[q] - M);
            float invS = 1.f / S;
            float* ws   = sm + SCR_OFF;       // 512 weights
            float* part = ws + 512;           // [8][132]
            for (int s = tid; s < 512; s += NTHR)
                ws[s] = expf(__ldcg(g_sc + b * 512 + s) - M) * invS;
            __syncthreads();
            int ug = tid & 31, ss = tid >> 5;
            int ub = uq * 128 + ug * 4;
            const float4* xc = (const float4*)(x + ((size_t)(b * 512) + ss * 64) * 512 + ub);
            const float* wp = ws + ss * 64;
            float4 acc = make_float4(0.f, 0.f, 0.f, 0.f);
            #pragma unroll 8
            for (int s2 = 0; s2 < 64; ++s2) {
                float4 v = __ldg(xc + (size_t)s2 * 128);
                float w = wp[s2];
                acc.x += w * v.x; acc.y += w * v.y;
                acc.z += w * v.z; acc.w += w * v.w;
            }
            *(float4*)(part + ss * AROW + ug * 4) = acc;
            __syncthreads();
            if (tid < 128) {
                float ctxv = 0.f;
                #pragma unroll
                for (int s = 0; s < 8; ++s) ctxv += part[s * AROW + tid];
                int idx = b * 512 + uq * 128 + tid;
                g_ctx[idx] = ctxv;
                g_hA[t & 1][idx] = __ldcg(&g_hA[t & 1][idx]) + ctxv;
                g_cA[idx]        = __ldcg(&g_cA[idx]) + ctxv;
            }
        }
        gbar();
    }

    // ---------- final dense 512->46 + softmax (hT = g_h2[1]) ----------
    if (blk < 32) {
        int b = blk;
        float* hs = sm + SCR_OFF;
        float* lg = hs + 512;
        for (int i = tid; i < 512; i += NTHR) hs[i] = __ldcg(g_h2[1] + b * 512 + i);
        __syncthreads();
        for (int v = warp; v < 46; v += 8) {
            float acc = 0.f;
            #pragma unroll 4
            for (int k = lane; k < 512; k += 32)
                acc += hs[k] * __ldg(Wd + (size_t)k * 46 + v);
            #pragma unroll
            for (int o = 16; o; o >>= 1) acc += __shfl_xor_sync(0xffffffffu, acc, o);
            if (lane == 0) lg[v] = acc + __ldg(bd + v);
        }
        __syncthreads();
        if (tid == 0) {
            float M = lg[0];
            for (int v = 1; v < 46; ++v) M = fmaxf(M, lg[v]);
            float S = 0.f;
            for (int v = 0; v < 46; ++v) { float e = expf(lg[v] - M); lg[v] = e; S += e; }
            float inv = 1.f / S;
            for (int v = 0; v < 46; ++v) out[b * 46 + v] = lg[v] * inv;
        }
    }
}

extern "C" void kernel_launch(void* const* d_in, const int* in_sizes, int n_in,
                              void* d_out, int out_size) {
    const float* x  = (const float*)d_in[0];
    const float* y  = (const float*)d_in[1];
    const float* Wa = (const float*)d_in[2];
    const float* Ra = (const float*)d_in[3];
    const float* ba = (const float*)d_in[4];
    const float* W1 = (const float*)d_in[5];
    const float* R1 = (const float*)d_in[6];
    const float* b1 = (const float*)d_in[7];
    const float* W2 = (const float*)d_in[8];
    const float* R2 = (const float*)d_in[9];
    const float* b2 = (const float*)d_in[10];
    const float* Wd = (const float*)d_in[11];
    const float* bd = (const float*)d_in[12];
    cudaFuncSetAttribute(spk, cudaFuncAttributeMaxDynamicSharedMemorySize, SMEM_BYTES);
    spk<<<NBLK, NTHR, SMEM_BYTES>>>(x, y, Wa, Ra, ba, W1, R1, b1, W2, R2, b2,
                                    Wd, bd, (float*)d_out);
}

// round 10
// speedup vs baseline: 1.6942x; 1.0715x over previous
#include <cuda_runtime.h>
#include <cuda_bf16.h>
#include <cstdint>

typedef unsigned long long ull;

#define NBLK 128
#define NTHR 512

// ---- persistent device state (no allocation) ----
__device__ float g_hA[2][16384];
__device__ float g_cA[16384];
__device__ float g_h1[2][16384];
__device__ float g_c1[16384];
__device__ float g_h2[2][16384];
__device__ float g_c2[16384];
__device__ float g_ctx[16384];
__device__ float g_sc[16384];
__device__ float g_pmax[128];
__device__ float g_psum[128];
__device__ unsigned g_cnt;
__device__ volatile unsigned g_gen;

// ---- dynamic smem layout (float offsets) ----
#define WJ      1028                  // padded k-stride per gate column
#define WCELL   (16 * WJ)             // 16448 floats per cell
#define A_OFF   (3 * WCELL)           // 49344: A chunk [32][132]
#define AROW    132
#define ZB_OFF  (A_OFF + 32 * AROW)   // partials [64][36] (kh*16+jj rows)
#define ZROW    36
#define SCR_OFF A_OFF                 // attention/final scratch overlays A+zb
#define SMEM_FLOATS (ZB_OFF + 64 * ZROW)
#define SMEM_BYTES  (SMEM_FLOATS * 4) // 223,488 B

__device__ __forceinline__ void ffma2(ull& d, ull a, ull b) {
    asm("fma.rn.f32x2 %0, %1, %2, %0;" : "+l"(d) : "l"(a), "l"(b));
}
__device__ __forceinline__ void fadd2(ull& d, ull a) {
    asm("add.rn.f32x2 %0, %1, %0;" : "+l"(d) : "l"(a));
}
__device__ __forceinline__ float2 ull2f2(ull v) {
    float2 r;
    asm("mov.b64 {%0, %1}, %2;" : "=f"(r.x), "=f"(r.y) : "l"(v));
    return r;
}

__device__ __forceinline__ void gbar() {
    __syncthreads();
    if (threadIdx.x == 0) {
        unsigned gen = g_gen;
        __threadfence();
        if (atomicAdd(&g_cnt, 1u) == (unsigned)(NBLK - 1)) {
            g_cnt = 0;
            __threadfence();
            g_gen = gen + 1u;
        } else {
            while (g_gen == gen) __nanosleep(64);
        }
        __threadfence();
    }
    __syncthreads();
}

// One LSTM cell. z = [in ; hrec] @ [W ; R] + bias (this CTA's 16 gate cols),
// CTA owns u in [u0, u0+4). Weights resident in smem, layout [jj][k] pad WJ.
// Thread GEMM map: kh = K-split (4), mp = m-quad (8), jj = col (16).
__device__ void cell(const float* __restrict__ in0, long long instride,
                     const float* __restrict__ hrec,
                     float* __restrict__ c_st, float* __restrict__ h_out,
                     const float* __restrict__ bias,
                     int cellIdx, int u0, float* __restrict__ sm) {
    float* Wsm = sm + cellIdx * WCELL;
    float* A_s = sm + A_OFF;
    float* zb  = sm + ZB_OFF;
    const int tid = threadIdx.x;
    const int am = tid >> 4, akq = tid & 15;          // staging decode
    const int kh = tid >> 7, r = tid & 127;           // gemm decode
    const int jj = r & 15, m0 = (r >> 4) << 2;

    float4 pf0, pf1;
    {   // fetch chunk 0 (k 0..127, from in0)
        const float* src = in0 + (long long)am * instride + akq * 4;
        pf0 = __ldcg((const float4*)src);
        pf1 = __ldcg((const float4*)(src + 64));
    }
    *(float4*)(A_s + am * AROW + akq * 4)      = pf0;
    *(float4*)(A_s + am * AROW + akq * 4 + 64) = pf1;
    __syncthreads();

    ull ax0 = 0, ax1 = 0, ax2 = 0, ax3 = 0;
    ull ay0 = 0, ay1 = 0, ay2 = 0, ay3 = 0;
    #pragma unroll 1
    for (int c = 0; c < 8; ++c) {
        if (c < 7) {
            const int cn = c + 1;
            const float* base = (cn < 4)
                ? (in0 + (long long)am * instride + cn * 128)
                : (hrec + am * 512 + (cn - 4) * 128);
            pf0 = __ldcg((const float4*)(base + akq * 4));
            pf1 = __ldcg((const float4*)(base + akq * 4 + 64));
        }
        const ulonglong2* Wp = (const ulonglong2*)(Wsm + jj * WJ + c * 128 + kh * 32);
        const float* Ab = A_s + m0 * AROW + kh * 32;
        #pragma unroll
        for (int kq = 0; kq < 8; ++kq) {
            ulonglong2 wv = Wp[kq];
            ulonglong2 a0 = *(const ulonglong2*)(Ab                + kq * 4);
            ulonglong2 a1 = *(const ulonglong2*)(Ab + 1 * AROW     + kq * 4);
            ulonglong2 a2 = *(const ulonglong2*)(Ab + 2 * AROW     + kq * 4);
            ulonglong2 a3 = *(const ulonglong2*)(Ab + 3 * AROW     + kq * 4);
            ffma2(ax0, a0.x, wv.x); ffma2(ax1, a1.x, wv.x);
            ffma2(ax2, a2.x, wv.x); ffma2(ax3, a3.x, wv.x);
            ffma2(ay0, a0.y, wv.y); ffma2(ay1, a1.y, wv.y);
            ffma2(ay2, a2.y, wv.y); ffma2(ay3, a3.y, wv.y);
        }
        __syncthreads();
        if (c < 7) {
            *(float4*)(A_s + am * AROW + akq * 4)      = pf0;
            *(float4*)(A_s + am * AROW + akq * 4 + 64) = pf1;
            __syncthreads();
        }
    }
    fadd2(ax0, ay0); fadd2(ax1, ay1); fadd2(ax2, ay2); fadd2(ax3, ay3);
    float2 p0 = ull2f2(ax0), p1 = ull2f2(ax1), p2 = ull2f2(ax2), p3 = ull2f2(ax3);
    float4 o = make_float4(p0.x + p0.y, p1.x + p1.y, p2.x + p2.y, p3.x + p3.y);
    *(float4*)(zb + ((kh << 4) + jj) * ZROW + m0) = o;
    __syncthreads();

    if (tid < 128) {
        int m = tid & 31, q = tid >> 5;
        int u = u0 + q;
        float zi = __ldg(bias + u);
        float zf = __ldg(bias + u + 512);
        float zg = __ldg(bias + u + 1024);
        float zo = __ldg(bias + u + 1536);
        #pragma unroll
        for (int k2 = 0; k2 < 4; ++k2) {
            zi += zb[((k2 << 4) + q     ) * ZROW + m];
            zf += zb[((k2 << 4) + q + 4 ) * ZROW + m];
            zg += zb[((k2 << 4) + q + 8 ) * ZROW + m];
            zo += zb[((k2 << 4) + q + 12) * ZROW + m];
        }
        float ig = 1.f / (1.f + expf(-zi));
        float fg = 1.f / (1.f + expf(-zf));
        float gg = tanhf(zg);
        float og = 1.f / (1.f + expf(-zo));
        float cv = fg * __ldcg(c_st + m * 512 + u) + ig * gg;
        c_st[m * 512 + u]  = cv;
        h_out[m * 512 + u] = og * tanhf(cv);
    }
    __syncthreads();
}

__global__ void __launch_bounds__(NTHR, 1)
spk(const float* __restrict__ x,  const float* __restrict__ y,
    const float* __restrict__ Wa, const float* __restrict__ Ra, const float* __restrict__ ba,
    const float* __restrict__ W1, const float* __restrict__ R1, const float* __restrict__ b1,
    const float* __restrict__ W2, const float* __restrict__ R2, const float* __restrict__ b2,
    const float* __restrict__ Wd, const float* __restrict__ bd,
    float* __restrict__ out) {
    extern __shared__ float sm[];
    const int blk = blockIdx.x, tid = threadIdx.x;
    const int lane = tid & 31, warp = tid >> 5;
    const int u0 = blk * 4;

    // ---- one-time persistent weight load: sm[c][jj][k] = stacked [W;R] col slice ----
    {
        const float* Ws[3] = {Wa, W1, W2};
        const float* Rs[3] = {Ra, R1, R2};
        #pragma unroll
        for (int c = 0; c < 3; ++c) {
            const float* Wc = Ws[c];
            const float* Rc = Rs[c];
            for (int i = tid; i < 16384; i += NTHR) {
                int k = i >> 4, j = i & 15;
                int col = u0 + (j & 3) + ((j >> 2) << 9);
                float v = (k < 512) ? __ldg(Wc + (size_t)k * 2048 + col)
                                    : __ldg(Rc + (size_t)(k - 512) * 2048 + col);
                sm[c * WCELL + j * WJ + k] = v;
            }
        }
    }

    // ---- zero initial states (globals persist across graph replays) ----
    {
        float* bufs[9] = {g_hA[0], g_hA[1], g_cA, g_h1[0], g_h1[1], g_c1,
                          g_h2[0], g_h2[1], g_c2};
        int base = blk * NTHR + tid;
        #pragma unroll
        for (int a = 0; a < 9; ++a)
            for (int i = base; i < 16384; i += NBLK * NTHR) bufs[a][i] = 0.f;
    }
    gbar();

    for (int t = 0; t < 130; ++t) {
        // ---------- stage 1: software-pipelined cells ----------
        if (t < 128)
            cell(y + (size_t)t * 512, 128LL * 512, g_hA[(t + 1) & 1],
                 g_cA, g_hA[t & 1], ba, 0, u0, sm);
        if (t >= 1 && t <= 128)
            cell(g_ctx, 512LL, g_h1[(t + 1) & 1],
                 g_c1, g_h1[t & 1], b1, 1, u0, sm);
        if (t >= 2)
            cell(g_h1[(t + 1) & 1], 512LL, g_h2[(t + 1) & 1],
                 g_c2, g_h2[t & 1], b2, 2, u0, sm);
        gbar();

        // ---------- phase S: scores + partial softmax stats ----------
        if (t < 128) {
            int b = blk >> 2, sq = blk & 3;
            float* hs   = sm + SCR_OFF;     // 512
            float* sc   = hs + 512;         // 128
            float* wred = sc + 128;         // 4
            const float* hA = g_hA[t & 1] + b * 512;
            hs[tid] = __ldcg(hA + tid);
            __syncthreads();
            const float4* hr = (const float4*)hs;
            float4 hv[4];
            #pragma unroll
            for (int i2 = 0; i2 < 4; ++i2) hv[i2] = hr[lane + 32 * i2];
            #pragma unroll 1
            for (int si = 0; si < 8; ++si) {
                int sl = warp + si * 16;
                const float4* xr = (const float4*)(x + ((size_t)(b * 512 + sq * 128 + sl)) * 512);
                float4 xv[4];
                #pragma unroll
                for (int i2 = 0; i2 < 4; ++i2) xv[i2] = __ldg(xr + lane + 32 * i2);
                float a0 = 0.f;
                #pragma unroll
                for (int i2 = 0; i2 < 4; ++i2)
                    a0 += xv[i2].x * hv[i2].x + xv[i2].y * hv[i2].y
                        + xv[i2].z * hv[i2].z + xv[i2].w * hv[i2].w;
                #pragma unroll
                for (int o = 16; o; o >>= 1) a0 += __shfl_xor_sync(0xffffffffu, a0, o);
                if (lane == 0) sc[sl] = a0;
            }
            __syncthreads();
            if (tid < 128) {
                float v = sc[tid];
                #pragma unroll
                for (int o = 16; o; o >>= 1) v = fmaxf(v, __shfl_xor_sync(0xffffffffu, v, o));
                if (lane == 0) wred[warp] = v;
            }
            __syncthreads();
            if (tid < 128) {
                float M = fmaxf(fmaxf(wred[0], wred[1]), fmaxf(wred[2], wred[3]));
                float e = expf(sc[tid] - M);
                #pragma unroll
                for (int o = 16; o; o >>= 1) e += __shfl_xor_sync(0xffffffffu, e, o);
                g_sc[b * 512 + sq * 128 + tid] = sc[tid];
                if (lane == 0) wred[warp] = e;
                __syncwarp();
                if (tid == 0) {
                    g_pmax[b * 4 + sq] = M;
                    g_psum[b * 4 + sq] = wred[0] + wred[1] + wred[2] + wred[3];
                }
            }
        }
        gbar();

        // ---------- phase X: global softmax, ctx slice, residual ----------
        if (t < 128) {
            int b = blk >> 2, uq = blk & 3;
            float pm[4], ps[4], M = -1e30f;
            #pragma unroll
            for (int q = 0; q < 4; ++q) {
                pm[q] = __ldcg(g_pmax + b * 4 + q);
                ps[q] = __ldcg(g_psum + b * 4 + q);
                M = fmaxf(M, pm[q]);
            }
            float S = 0.f;
            #pragma unroll
            for (int q = 0; q < 4; ++q) S += ps[q] * expf(pm[q] - M);
            float invS = 1.f / S;
            float* ws   = sm + SCR_OFF;       // 512 weights
            float* part = ws + 512;           // [16][132]
            ws[tid] = expf(__ldcg(g_sc + b * 512 + tid) - M) * invS;
            __syncthreads();
            int ug = tid & 31, ss = tid >> 5;
            int ub = uq * 128 + ug * 4;
            const float4* xc = (const float4*)(x + ((size_t)(b * 512) + ss * 32) * 512 + ub);
            const float* wp = ws + ss * 32;
            float4 acc = make_float4(0.f, 0.f, 0.f, 0.f);
            #pragma unroll 8
            for (int s2 = 0; s2 < 32; ++s2) {
                float4 v = __ldg(xc + (size_t)s2 * 128);
                float w = wp[s2];
                acc.x += w * v.x; acc.y += w * v.y;
                acc.z += w * v.z; acc.w += w * v.w;
            }
            *(float4*)(part + ss * AROW + ug * 4) = acc;
            __syncthreads();
            if (tid < 128) {
                float ctxv = 0.f;
                #pragma unroll
                for (int s = 0; s < 16; ++s) ctxv += part[s * AROW + tid];
                int idx = b * 512 + uq * 128 + tid;
                g_ctx[idx] = ctxv;
                g_hA[t & 1][idx] = __ldcg(&g_hA[t & 1][idx]) + ctxv;
                g_cA[idx]        = __ldcg(&g_cA[idx]) + ctxv;
            }
        }
        gbar();
    }

    // ---------- final dense 512->46 + softmax (hT = g_h2[1]) ----------
    if (blk < 32) {
        int b = blk;
        float* hs = sm + SCR_OFF;
        float* lg = hs + 512;
        hs[tid] = __ldcg(g_h2[1] + b * 512 + tid);
        __syncthreads();
        for (int v = warp; v < 46; v += 16) {
            float acc = 0.f;
            #pragma unroll 4
            for (int k = lane; k < 512; k += 32)
                acc += hs[k] * __ldg(Wd + (size_t)k * 46 + v);
            #pragma unroll
            for (int o = 16; o; o >>= 1) acc += __shfl_xor_sync(0xffffffffu, acc, o);
            if (lane == 0) lg[v] = acc + __ldg(bd + v);
        }
        __syncthreads();
        if (tid == 0) {
            float M = lg[0];
            for (int v = 1; v < 46; ++v) M = fmaxf(M, lg[v]);
            float S = 0.f;
            for (int v = 0; v < 46; ++v) { float e = expf(lg[v] - M); lg[v] = e; S += e; }
            float inv = 1.f / S;
            for (int v = 0; v < 46; ++v) out[b * 46 + v] = lg[v] * inv;
        }
    }
}

extern "C" void kernel_launch(void* const* d_in, const int* in_sizes, int n_in,
                              void* d_out, int out_size) {
    const float* x  = (const float*)d_in[0];
    const float* y  = (const float*)d_in[1];
    const float* Wa = (const float*)d_in[2];
    const float* Ra = (const float*)d_in[3];
    const float* ba = (const float*)d_in[4];
    const float* W1 = (const float*)d_in[5];
    const float* R1 = (const float*)d_in[6];
    const float* b1 = (const float*)d_in[7];
    const float* W2 = (const float*)d_in[8];
    const float* R2 = (const float*)d_in[9];
    const float* b2 = (const float*)d_in[10];
    const float* Wd = (const float*)d_in[11];
    const float* bd = (const float*)d_in[12];
    cudaFuncSetAttribute(spk, cudaFuncAttributeMaxDynamicSharedMemorySize, SMEM_BYTES);
    spk<<<NBLK, NTHR, SMEM_BYTES>>>(x, y, Wa, Ra, ba, W1, R1, b1, W2, R2, b2,
                                    Wd, bd, (float*)d_out);
}

// round 12
// speedup vs baseline: 1.9678x; 1.1615x over previous
#include <cuda_runtime.h>
#include <cuda_bf16.h>
#include <cstdint>

typedef unsigned long long ull;

#define NBLK 128
#define NTHR 512

// ---- persistent device state (no allocation) ----
__device__ float g_hA[2][16384];
__device__ float g_cA[16384];
__device__ float g_h1[2][16384];
__device__ float g_c1[16384];
__device__ float g_h2[2][16384];
__device__ float g_c2[16384];
__device__ float g_ctx[16384];
__device__ float g_sc[16384];
__device__ float g_pmax[128];
__device__ float g_psum[128];
__device__ unsigned g_cnt;
__device__ volatile unsigned g_gen;

// ---- dynamic smem layout (float offsets) ----
#define WCELL   16384                 // [jj 16][k 1024], unpadded (16B aligned)
#define A_OFF   (3 * WCELL)           // 49152: A chunk [32][128] XOR-swizzled (4096 floats)
#define P_OFF   A_OFF                 // kh-tree partials [8][512] overlay A
#define ZB_OFF  (A_OFF + 4096)        // final z [16][36]
#define SCR_OFF A_OFF                 // attention/final scratch overlays A
#define AROW    132                   // attention partial row stride
#define SMEM_FLOATS (ZB_OFF + 576)
#define SMEM_BYTES  (SMEM_FLOATS * 4) // 215,296 B

__device__ __forceinline__ void ffma2(ull& d, ull a, ull b) {
    asm("fma.rn.f32x2 %0, %1, %2, %0;" : "+l"(d) : "l"(a), "l"(b));
}
__device__ __forceinline__ float2 ull2f2(ull v) {
    float2 r;
    asm("mov.b64 {%0, %1}, %2;" : "=f"(r.x), "=f"(r.y) : "l"(v));
    return r;
}

__device__ __forceinline__ void gbar() {
    __syncthreads();
    if (threadIdx.x == 0) {
        unsigned gen = g_gen;
        __threadfence();
        if (atomicAdd(&g_cnt, 1u) == (unsigned)(NBLK - 1)) {
            g_cnt = 0;
            __threadfence();
            g_gen = gen + 1u;
        } else {
            while (g_gen == gen) __nanosleep(32);
        }
        __threadfence();
    }
    __syncthreads();
}

// One LSTM cell. z = [in ; hrec] @ [W ; R] + bias (this CTA's 16 gate cols),
// CTA owns u in [u0, u0+4). Weights resident in smem, layout [jj][k 0..1023].
// Map: warp = kh (16 k-slices, 8 k per 128-k chunk); lane = mg(8) | colg(4)<<3.
// Tile per thread: 4 cols x 4 rows. A buffer XOR-swizzled (chunk ^= row>>2).
__device__ void cell(const float* __restrict__ in0, long long instride,
                     const float* __restrict__ hrec,
                     float* __restrict__ c_st, float* __restrict__ h_out,
                     const float* __restrict__ bias,
                     int cellIdx, int u0, float* __restrict__ sm) {
    float* Wsm = sm + cellIdx * WCELL;
    float* A_s = sm + A_OFF;
    float* P   = sm + P_OFF;
    float* zb  = sm + ZB_OFF;
    const int tid = threadIdx.x;
    const int am = tid >> 4, akq = tid & 15;     // staging decode
    const int lane = tid & 31, kh = tid >> 5;
    const int mg = lane & 7, colg = lane >> 3;
    const int m0 = mg << 2, jbase = colg << 2;
    const int sta = am * 128 + ((akq ^ (am >> 2)) << 2);  // swizzled staging addr

    float4 pf0, pf1;
    {   // fetch + stage chunk 0 (k 0..127, from in0)
        const float* src = in0 + (long long)am * instride + akq * 4;
        pf0 = __ldcg((const float4*)src);
        pf1 = __ldcg((const float4*)(src + 64));
    }
    *(float4*)(A_s + sta)      = pf0;
    *(float4*)(A_s + sta + 64) = pf1;
    __syncthreads();

    ull acc00 = 0, acc01 = 0, acc02 = 0, acc03 = 0;
    ull acc10 = 0, acc11 = 0, acc12 = 0, acc13 = 0;
    ull acc20 = 0, acc21 = 0, acc22 = 0, acc23 = 0;
    ull acc30 = 0, acc31 = 0, acc32 = 0, acc33 = 0;

    #pragma unroll 1
    for (int c = 0; c < 8; ++c) {
        if (c < 7) {
            const int cn = c + 1;
            const float* base = (cn < 4)
                ? (in0 + (long long)am * instride + cn * 128)
                : (hrec + am * 512 + (cn - 4) * 128);
            pf0 = __ldcg((const float4*)(base + akq * 4));
            pf1 = __ldcg((const float4*)(base + akq * 4 + 64));
        }
        const float* Wb = Wsm + jbase * 1024 + c * 128 + kh * 8;
        #pragma unroll
        for (int kq = 0; kq < 2; ++kq) {
            const int kc = kh * 2 + kq;
            ulonglong2 w0 = *(const ulonglong2*)(Wb            + kq * 4);
            ulonglong2 w1 = *(const ulonglong2*)(Wb + 1024     + kq * 4);
            ulonglong2 w2 = *(const ulonglong2*)(Wb + 2 * 1024 + kq * 4);
            ulonglong2 w3 = *(const ulonglong2*)(Wb + 3 * 1024 + kq * 4);
            const int sw = (kc ^ mg) << 2;
            ulonglong2 a0 = *(const ulonglong2*)(A_s + (m0    ) * 128 + sw);
            ulonglong2 a1 = *(const ulonglong2*)(A_s + (m0 + 1) * 128 + sw);
            ulonglong2 a2 = *(const ulonglong2*)(A_s + (m0 + 2) * 128 + sw);
            ulonglong2 a3 = *(const ulonglong2*)(A_s + (m0 + 3) * 128 + sw);
            // x-pass (k, k+1)
            ffma2(acc00, a0.x, w0.x); ffma2(acc01, a1.x, w0.x);
            ffma2(acc02, a2.x, w0.x); ffma2(acc03, a3.x, w0.x);
            ffma2(acc10, a0.x, w1.x); ffma2(acc11, a1.x, w1.x);
            ffma2(acc12, a2.x, w1.x); ffma2(acc13, a3.x, w1.x);
            ffma2(acc20, a0.x, w2.x); ffma2(acc21, a1.x, w2.x);
            ffma2(acc22, a2.x, w2.x); ffma2(acc23, a3.x, w2.x);
            ffma2(acc30, a0.x, w3.x); ffma2(acc31, a1.x, w3.x);
            ffma2(acc32, a2.x, w3.x); ffma2(acc33, a3.x, w3.x);
            // y-pass (k+2, k+3)
            ffma2(acc00, a0.y, w0.y); ffma2(acc01, a1.y, w0.y);
            ffma2(acc02, a2.y, w0.y); ffma2(acc03, a3.y, w0.y);
            ffma2(acc10, a0.y, w1.y); ffma2(acc11, a1.y, w1.y);
            ffma2(acc12, a2.y, w1.y); ffma2(acc13, a3.y, w1.y);
            ffma2(acc20, a0.y, w2.y); ffma2(acc21, a1.y, w2.y);
            ffma2(acc22, a2.y, w2.y); ffma2(acc23, a3.y, w2.y);
            ffma2(acc30, a0.y, w3.y); ffma2(acc31, a1.y, w3.y);
            ffma2(acc32, a2.y, w3.y); ffma2(acc33, a3.y, w3.y);
        }
        __syncthreads();
        if (c < 7) {
            *(float4*)(A_s + sta)      = pf0;
            *(float4*)(A_s + sta + 64) = pf1;
            __syncthreads();
        }
    }

    // horizontal combine -> float4 per col (m0..m0+3)
    float4 vv0, vv1, vv2, vv3;
    {
        float2 t;
        t = ull2f2(acc00); vv0.x = t.x + t.y;
        t = ull2f2(acc01); vv0.y = t.x + t.y;
        t = ull2f2(acc02); vv0.z = t.x + t.y;
        t = ull2f2(acc03); vv0.w = t.x + t.y;
        t = ull2f2(acc10); vv1.x = t.x + t.y;
        t = ull2f2(acc11); vv1.y = t.x + t.y;
        t = ull2f2(acc12); vv1.z = t.x + t.y;
        t = ull2f2(acc13); vv1.w = t.x + t.y;
        t = ull2f2(acc20); vv2.x = t.x + t.y;
        t = ull2f2(acc21); vv2.y = t.x + t.y;
        t = ull2f2(acc22); vv2.z = t.x + t.y;
        t = ull2f2(acc23); vv2.w = t.x + t.y;
        t = ull2f2(acc30); vv3.x = t.x + t.y;
        t = ull2f2(acc31); vv3.y = t.x + t.y;
        t = ull2f2(acc32); vv3.z = t.x + t.y;
        t = ull2f2(acc33); vv3.w = t.x + t.y;
    }

    // kh-tree reduce over 16 warps (P overlays dead A region, 8 slots of 512)
    #pragma unroll
    for (int step = 8; step >= 1; step >>= 1) {
        if (kh >= step && kh < 2 * step) {
            float* pd = P + (kh - step) * 512;
            *(float4*)(pd + (jbase    ) * 32 + m0) = vv0;
            *(float4*)(pd + (jbase + 1) * 32 + m0) = vv1;
            *(float4*)(pd + (jbase + 2) * 32 + m0) = vv2;
            *(float4*)(pd + (jbase + 3) * 32 + m0) = vv3;
        }
        __syncthreads();
        if (kh < step) {
            const float* pr = P + kh * 512;
            float4 o;
            o = *(const float4*)(pr + (jbase    ) * 32 + m0);
            vv0.x += o.x; vv0.y += o.y; vv0.z += o.z; vv0.w += o.w;
            o = *(const float4*)(pr + (jbase + 1) * 32 + m0);
            vv1.x += o.x; vv1.y += o.y; vv1.z += o.z; vv1.w += o.w;
            o = *(const float4*)(pr + (jbase + 2) * 32 + m0);
            vv2.x += o.x; vv2.y += o.y; vv2.z += o.z; vv2.w += o.w;
            o = *(const float4*)(pr + (jbase + 3) * 32 + m0);
            vv3.x += o.x; vv3.y += o.y; vv3.z += o.z; vv3.w += o.w;
        }
        __syncthreads();
    }
    if (kh == 0) {
        *(float4*)(zb + (jbase    ) * 36 + m0) = vv0;
        *(float4*)(zb + (jbase + 1) * 36 + m0) = vv1;
        *(float4*)(zb + (jbase + 2) * 36 + m0) = vv2;
        *(float4*)(zb + (jbase + 3) * 36 + m0) = vv3;
    }
    __syncthreads();

    if (tid < 128) {
        int m = tid & 31, q = tid >> 5;
        int u = u0 + q;
        float zi = zb[(q     ) * 36 + m] + __ldg(bias + u);
        float zf = zb[(4  + q) * 36 + m] + __ldg(bias + u + 512);
        float zg = zb[(8  + q) * 36 + m] + __ldg(bias + u + 1024);
        float zo = zb[(12 + q) * 36 + m] + __ldg(bias + u + 1536);
        float ig = 1.f / (1.f + expf(-zi));
        float fg = 1.f / (1.f + expf(-zf));
        float gg = tanhf(zg);
        float og = 1.f / (1.f + expf(-zo));
        float cv = fg * __ldcg(c_st + m * 512 + u) + ig * gg;
        c_st[m * 512 + u]  = cv;
        h_out[m * 512 + u] = og * tanhf(cv);
    }
    __syncthreads();
}

__global__ void __launch_bounds__(NTHR, 1)
spk(const float* __restrict__ x,  const float* __restrict__ y,
    const float* __restrict__ Wa, const float* __restrict__ Ra, const float* __restrict__ ba,
    const float* __restrict__ W1, const float* __restrict__ R1, const float* __restrict__ b1,
    const float* __restrict__ W2, const float* __restrict__ R2, const float* __restrict__ b2,
    const float* __restrict__ Wd, const float* __restrict__ bd,
    float* __restrict__ out) {
    extern __shared__ float sm[];
    const int blk = blockIdx.x, tid = threadIdx.x;
    const int lane = tid & 31, warp = tid >> 5;
    const int u0 = blk * 4;

    // ---- one-time persistent weight load: sm[c][jj][k] = stacked [W;R] col slice ----
    {
        const float* Ws[3] = {Wa, W1, W2};
        const float* Rs[3] = {Ra, R1, R2};
        #pragma unroll
        for (int c = 0; c < 3; ++c) {
            const float* Wc = Ws[c];
            const float* Rc = Rs[c];
            for (int i = tid; i < 16384; i += NTHR) {
                int j = i >> 10, k = i & 1023;
                int col = u0 + (j & 3) + ((j >> 2) << 9);
                float v = (k < 512) ? __ldg(Wc + (size_t)k * 2048 + col)
                                    : __ldg(Rc + (size_t)(k - 512) * 2048 + col);
                sm[c * WCELL + j * 1024 + k] = v;
            }
        }
    }

    // ---- zero initial states (globals persist across graph replays) ----
    {
        float* bufs[9] = {g_hA[0], g_hA[1], g_cA, g_h1[0], g_h1[1], g_c1,
                          g_h2[0], g_h2[1], g_c2};
        int base = blk * NTHR + tid;
        #pragma unroll
        for (int a = 0; a < 9; ++a)
            for (int i = base; i < 16384; i += NBLK * NTHR) bufs[a][i] = 0.f;
    }
    gbar();

    for (int t = 0; t < 130; ++t) {
        // ---------- stage 1: software-pipelined cells ----------
        if (t < 128)
            cell(y + (size_t)t * 512, 128LL * 512, g_hA[(t + 1) & 1],
                 g_cA, g_hA[t & 1], ba, 0, u0, sm);
        if (t >= 1 && t <= 128)
            cell(g_ctx, 512LL, g_h1[(t + 1) & 1],
                 g_c1, g_h1[t & 1], b1, 1, u0, sm);
        if (t >= 2)
            cell(g_h1[(t + 1) & 1], 512LL, g_h2[(t + 1) & 1],
                 g_c2, g_h2[t & 1], b2, 2, u0, sm);
        gbar();

        // ---------- phase S: scores + partial softmax stats ----------
        if (t < 128) {
            int b = blk >> 2, sq = blk & 3;
            float* hs   = sm + SCR_OFF;     // 512
            float* sc   = hs + 512;         // 128
            float* wred = sc + 128;         // 4
            const float* hA = g_hA[t & 1] + b * 512;
            hs[tid] = __ldcg(hA + tid);
            __syncthreads();
            const float4* hr = (const float4*)hs;
            float4 hv[4];
            #pragma unroll
            for (int i2 = 0; i2 < 4; ++i2) hv[i2] = hr[lane + 32 * i2];
            #pragma unroll 1
            for (int si = 0; si < 8; si += 2) {
                int sl0 = warp + si * 16;
                const float4* xr0 = (const float4*)(x + ((size_t)(b * 512 + sq * 128 + sl0)) * 512);
                const float4* xr1 = xr0 + 16 * 128;
                float4 x0[4], x1[4];
                #pragma unroll
                for (int i2 = 0; i2 < 4; ++i2) {
                    x0[i2] = __ldg(xr0 + lane + 32 * i2);
                    x1[i2] = __ldg(xr1 + lane + 32 * i2);
                }
                float a0 = 0.f, a1 = 0.f;
                #pragma unroll
                for (int i2 = 0; i2 < 4; ++i2) {
                    a0 += x0[i2].x * hv[i2].x + x0[i2].y * hv[i2].y
                        + x0[i2].z * hv[i2].z + x0[i2].w * hv[i2].w;
                    a1 += x1[i2].x * hv[i2].x + x1[i2].y * hv[i2].y
                        + x1[i2].z * hv[i2].z + x1[i2].w * hv[i2].w;
                }
                #pragma unroll
                for (int o = 16; o; o >>= 1) {
                    a0 += __shfl_xor_sync(0xffffffffu, a0, o);
                    a1 += __shfl_xor_sync(0xffffffffu, a1, o);
                }
                if (lane == 0) { sc[sl0] = a0; sc[sl0 + 16] = a1; }
            }
            __syncthreads();
            if (tid < 128) {
                float v = sc[tid];
                #pragma unroll
                for (int o = 16; o; o >>= 1) v = fmaxf(v, __shfl_xor_sync(0xffffffffu, v, o));
                if (lane == 0) wred[warp] = v;
            }
            __syncthreads();
            if (tid < 128) {
                float M = fmaxf(fmaxf(wred[0], wred[1]), fmaxf(wred[2], wred[3]));
                float e = expf(sc[tid] - M);
                #pragma unroll
                for (int o = 16; o; o >>= 1) e += __shfl_xor_sync(0xffffffffu, e, o);
                g_sc[b * 512 + sq * 128 + tid] = sc[tid];
                if (lane == 0) wred[warp] = e;
                __syncwarp();
                if (tid == 0) {
                    g_pmax[b * 4 + sq] = M;
                    g_psum[b * 4 + sq] = wred[0] + wred[1] + wred[2] + wred[3];
                }
            }
        }
        gbar();

        // ---------- phase X: global softmax, ctx slice, residual ----------
        if (t < 128) {
            int b = blk >> 2, uq = blk & 3;
            float pm[4], ps[4], M = -1e30f;
            #pragma unroll
            for (int q = 0; q < 4; ++q) {
                pm[q] = __ldcg(g_pmax + b * 4 + q);
                ps[q] = __ldcg(g_psum + b * 4 + q);
                M = fmaxf(M, pm[q]);
            }
            float S = 0.f;
            #pragma unroll
            for (int q = 0; q < 4; ++q) S += ps[q] * expf(pm[q] - M);
            float invS = 1.f / S;
            float* ws   = sm + SCR_OFF;       // 512 weights
            float* part = ws + 512;           // [16][132]
            ws[tid] = expf(__ldcg(g_sc + b * 512 + tid) - M) * invS;
            __syncthreads();
            int ug = tid & 31, ss = tid >> 5;
            int ub = uq * 128 + ug * 4;
            const float4* xc = (const float4*)(x + ((size_t)(b * 512) + ss * 32) * 512 + ub);
            const float* wp = ws + ss * 32;
            float4 acc = make_float4(0.f, 0.f, 0.f, 0.f);
            #pragma unroll 8
            for (int s2 = 0; s2 < 32; ++s2) {
                float4 v = __ldg(xc + (size_t)s2 * 128);
                float w = wp[s2];
                acc.x += w * v.x; acc.y += w * v.y;
                acc.z += w * v.z; acc.w += w * v.w;
            }
            *(float4*)(part + ss * AROW + ug * 4) = acc;
            __syncthreads();
            if (tid < 128) {
                float ctxv = 0.f;
                #pragma unroll
                for (int s = 0; s < 16; ++s) ctxv += part[s * AROW + tid];
                int idx = b * 512 + uq * 128 + tid;
                g_ctx[idx] = ctxv;
                g_hA[t & 1][idx] = __ldcg(&g_hA[t & 1][idx]) + ctxv;
                g_cA[idx]        = __ldcg(&g_cA[idx]) + ctxv;
            }
        }
        gbar();
    }

    // ---------- final dense 512->46 + softmax (hT = g_h2[1]) ----------
    if (blk < 32) {
        int b = blk;
        float* hs = sm + SCR_OFF;
        float* lg = hs + 512;
        hs[tid] = __ldcg(g_h2[1] + b * 512 + tid);
        __syncthreads();
        for (int v = warp; v < 46; v += 16) {
            float acc = 0.f;
            #pragma unroll 4
            for (int k = lane; k < 512; k += 32)
                acc += hs[k] * __ldg(Wd + (size_t)k * 46 + v);
            #pragma unroll
            for (int o = 16; o; o >>= 1) acc += __shfl_xor_sync(0xffffffffu, acc, o);
            if (lane == 0) lg[v] = acc + __ldg(bd + v);
        }
        __syncthreads();
        if (tid == 0) {
            float M = lg[0];
            for (int v = 1; v < 46; ++v) M = fmaxf(M, lg[v]);
            float S = 0.f;
            for (int v = 0; v < 46; ++v) { float e = expf(lg[v] - M); lg[v] = e; S += e; }
            float inv = 1.f / S;
            for (int v = 0; v < 46; ++v) out[b * 46 + v] = lg[v] * inv;
        }
    }
}

extern "C" void kernel_launch(void* const* d_in, const int* in_sizes, int n_in,
                              void* d_out, int out_size) {
    const float* x  = (const float*)d_in[0];
    const float* y  = (const float*)d_in[1];
    const float* Wa = (const float*)d_in[2];
    const float* Ra = (const float*)d_in[3];
    const float* ba = (const float*)d_in[4];
    const float* W1 = (const float*)d_in[5];
    const float* R1 = (const float*)d_in[6];
    const float* b1 = (const float*)d_in[7];
    const float* W2 = (const float*)d_in[8];
    const float* R2 = (const float*)d_in[9];
    const float* b2 = (const float*)d_in[10];
    const float* Wd = (const float*)d_in[11];
    const float* bd = (const float*)d_in[12];
    cudaFuncSetAttribute(spk, cudaFuncAttributeMaxDynamicSharedMemorySize, SMEM_BYTES);
    spk<<<NBLK, NTHR, SMEM_BYTES>>>(x, y, Wa, Ra, ba, W1, R1, b1, W2, R2, b2,
                                    Wd, bd, (float*)d_out);
}